// round 7
// baseline (speedup 1.0000x reference)
#include <cuda_runtime.h>

// Fully-fused 4-level 2D Haar DWT — 192-thread / 10-blocks-per-SM version.
// Input x: (32, 3, 512, 512) fp32.
// Output: concat of t1 (32,12,256,256), t2 (32,12,128,128),
//         t3 (32,12,64,64), t4 (32,12,32,32).
// One block = one 128x128 input tile of one (batch,color) plane; LL bands
// cascade through shared memory (22 KB).
// 192 threads (6 warps) x 10 blocks/SM = 60 warps/SM, 1480 concurrent blocks
// for a 1536-block grid -> 1.04 waves (vs 1.30 at 256 threads).
// Level 4 computes r,g only (b4 = g4 duplicated into channels 8..11).

#define HAAR(a_, b_, c_, d_, LL, LH, HL, HH)      \
    do {                                          \
        float L0 = (a_ + c_) * 0.5f;              \
        float L1 = (b_ + d_) * 0.5f;              \
        float H0 = fabsf(a_ - c_);                \
        float H1 = fabsf(b_ - d_);                \
        LL = (L0 + L1) * 0.5f;                    \
        LH = fabsf(L0 - L1);                      \
        HL = (H0 + H1) * 0.5f;                    \
        HH = fabsf(H0 - H1);                      \
    } while (0)

__global__ __launch_bounds__(192, 10) void dwt_fused_kernel(
    const float* __restrict__ x, float* __restrict__ out)
{
    __shared__ float s1[64 * 64];   // 16 KB, L1 LL
    __shared__ float s2[32 * 32];   //  4 KB, L2 LL
    __shared__ float s3[16 * 16];   //  1 KB, L3 LL

    const int tid = threadIdx.x;
    const int tj  = blockIdx.x;       // 0..3  (column tile)
    const int ti  = blockIdx.y;       // 0..3  (row tile)
    const int bc  = blockIdx.z;       // 0..95
    const int b   = bc / 3;
    const int c   = bc % 3;

    const long S1 = 32L * 12 * 256 * 256;
    const long S2 = 32L * 12 * 128 * 128;
    const long S3 = 32L * 12 * 64 * 64;

    // ---------------- Level 1: x -> t1 (64x64 outputs) ---------------------
    {
        const float* ip = x + (long)b * (3 * 512 * 512)
                            + (long)c * (512 * 512)
                            + (long)(ti * 128) * 512 + tj * 128;
        float* o1 = out + (long)b * (12 * 65536)
                        + (long)(c * 4) * 65536
                        + (long)(ti * 64) * 256 + tj * 64;

        const int tx = tid & 63;       // column 0..63
        const int ty = tid >> 6;       // 0..2

        #pragma unroll 2
        for (int r = ty; r < 64; r += 3) {
            const float2* r0 = reinterpret_cast<const float2*>(ip + (long)(2 * r) * 512);
            const float2* r1 = reinterpret_cast<const float2*>(ip + (long)(2 * r + 1) * 512);
            float2 t = __ldg(&r0[tx]);
            float2 u = __ldg(&r1[tx]);

            float LL, LH, HL, HH;
            HAAR(t.x, t.y, u.x, u.y, LL, LH, HL, HH);

            float* orow = o1 + (long)r * 256 + tx;
            orow[0]          = LL;
            orow[65536]      = LH;
            orow[2 * 65536]  = HL;
            orow[3 * 65536]  = HH;
            s1[r * 64 + tx]  = LL;
        }
    }
    __syncthreads();

    // ---------------- Level 2: s1 -> t2 (32x32 outputs) --------------------
    {
        float* o2 = out + S1 + (long)b * (12 * 16384)
                        + (long)(c * 4) * 16384
                        + (long)(ti * 32) * 128 + tj * 32;

        const int tx = tid & 31;       // column 0..31
        const int ty = tid >> 5;       // 0..5
        const float2* s1v = reinterpret_cast<const float2*>(s1);

        for (int r = ty; r < 32; r += 6) {
            float2 t = s1v[(2 * r) * 32 + tx];
            float2 u = s1v[(2 * r + 1) * 32 + tx];

            float LL, LH, HL, HH;
            HAAR(t.x, t.y, u.x, u.y, LL, LH, HL, HH);

            float* orow = o2 + (long)r * 128 + tx;
            orow[0]          = LL;
            orow[16384]      = LH;
            orow[2 * 16384]  = HL;
            orow[3 * 16384]  = HH;
            s2[r * 32 + tx]  = LL;
        }
    }
    __syncthreads();

    // ---------------- Level 3: s2 -> t3 (16x16 outputs) --------------------
    {
        float* o3 = out + S1 + S2 + (long)b * (12 * 4096)
                        + (long)(c * 4) * 4096
                        + (long)(ti * 16) * 64 + tj * 16;

        const int tx = tid & 15;       // 0..15
        const int ty = tid >> 4;       // 0..11
        const float2* s2v = reinterpret_cast<const float2*>(s2);

        for (int r = ty; r < 16; r += 12) {
            float2 t = s2v[(2 * r) * 16 + tx];
            float2 u = s2v[(2 * r + 1) * 16 + tx];

            float LL, LH, HL, HH;
            HAAR(t.x, t.y, u.x, u.y, LL, LH, HL, HH);

            float* orow = o3 + (long)r * 64 + tx;
            orow[0]         = LL;
            orow[4096]      = LH;
            orow[2 * 4096]  = HL;
            orow[3 * 4096]  = HH;
            s3[r * 16 + tx] = LL;
        }
    }
    __syncthreads();

    // ---------------- Level 4: s3 -> t4 (8x8 outputs, r/g only) ------------
    if (tid < 64 && c < 2) {
        float* o4 = out + S1 + S2 + S3 + (long)b * (12 * 1024)
                        + (long)(c * 4) * 1024
                        + (long)(ti * 8) * 32 + tj * 8;

        const int tx = tid & 7;        // 0..7
        const int ty = tid >> 3;       // 0..7
        const float2* s3v = reinterpret_cast<const float2*>(s3);

        float2 t = s3v[(2 * ty) * 8 + tx];
        float2 u = s3v[(2 * ty + 1) * 8 + tx];

        float LL, LH, HL, HH;
        HAAR(t.x, t.y, u.x, u.y, LL, LH, HL, HH);

        float* orow = o4 + (long)ty * 32 + tx;
        orow[0]         = LL;
        orow[1024]      = LH;
        orow[2 * 1024]  = HL;
        orow[3 * 1024]  = HH;

        if (c == 1) {                  // b4 = g4 -> channels 8..11
            float* orow2 = orow + 4 * 1024;
            orow2[0]         = LL;
            orow2[1024]      = LH;
            orow2[2 * 1024]  = HL;
            orow2[3 * 1024]  = HH;
        }
    }
}

extern "C" void kernel_launch(void* const* d_in, const int* in_sizes, int n_in,
                              void* d_out, int out_size)
{
    const float* x = (const float*)d_in[0];
    float* out = (float*)d_out;

    dim3 block(192, 1, 1);
    dim3 grid(4, 4, 96);
    dwt_fused_kernel<<<grid, block>>>(x, out);
}

// round 8
// speedup vs baseline: 1.1497x; 1.1497x over previous
#include <cuda_runtime.h>

// Fully-fused 4-level 2D Haar DWT — R2 structure + doubled load MLP in L1.
// Input x: (32, 3, 512, 512) fp32.
// Output: concat of t1 (32,12,256,256), t2 (32,12,128,128),
//         t3 (32,12,64,64), t4 (32,12,32,32).
// One block = one 128x128 input tile of one (batch,color) plane; LL bands
// cascade through shared memory. Level 1 processes TWO output rows per
// iteration with all 4 independent LDG.64 issued before compute/stores,
// doubling per-warp outstanding reads (latency cover for ~6 TB/s read-side).
// Level 4 computes r,g only (b4 = g4 duplicated into channels 8..11).

#define HAAR(a_, b_, c_, d_, LL, LH, HL, HH)      \
    do {                                          \
        float L0 = (a_ + c_) * 0.5f;              \
        float L1 = (b_ + d_) * 0.5f;              \
        float H0 = fabsf(a_ - c_);                \
        float H1 = fabsf(b_ - d_);                \
        LL = (L0 + L1) * 0.5f;                    \
        LH = fabsf(L0 - L1);                      \
        HL = (H0 + H1) * 0.5f;                    \
        HH = fabsf(H0 - H1);                      \
    } while (0)

__global__ __launch_bounds__(256) void dwt_fused_kernel(
    const float* __restrict__ x, float* __restrict__ out)
{
    __shared__ float s1[64 * 64];   // 16 KB, L1 LL
    __shared__ float s2[32 * 32];   //  4 KB, L2 LL
    __shared__ float s3[16 * 16];   //  1 KB, L3 LL

    const int tid = threadIdx.x;
    const int tj  = blockIdx.x;       // 0..3  (column tile)
    const int ti  = blockIdx.y;       // 0..3  (row tile)
    const int bc  = blockIdx.z;       // 0..95
    const int b   = bc / 3;
    const int c   = bc % 3;

    const long S1 = 32L * 12 * 256 * 256;
    const long S2 = 32L * 12 * 128 * 128;
    const long S3 = 32L * 12 * 64 * 64;

    // ---- Level 1: x -> t1.  2 output rows per iteration, 4 LDG in flight --
    {
        const float* ip = x + (long)b * (3 * 512 * 512)
                            + (long)c * (512 * 512)
                            + (long)(ti * 128) * 512 + tj * 128;
        float* o1 = out + (long)b * (12 * 65536)
                        + (long)(c * 4) * 65536
                        + (long)(ti * 64) * 256 + tj * 64;

        const int tx = tid & 63;       // column 0..63
        const int ty = tid >> 6;       // 0..3

        #pragma unroll
        for (int k = 0; k < 8; k++) {
            const int ra = 8 * k + ty;        // first output row
            const int rb = ra + 4;            // second output row

            // Front-load 4 independent LDG.64
            const float2* a0 = reinterpret_cast<const float2*>(ip + (long)(2 * ra) * 512);
            const float2* a1 = reinterpret_cast<const float2*>(ip + (long)(2 * ra + 1) * 512);
            const float2* b0 = reinterpret_cast<const float2*>(ip + (long)(2 * rb) * 512);
            const float2* b1 = reinterpret_cast<const float2*>(ip + (long)(2 * rb + 1) * 512);
            float2 pa = __ldg(&a0[tx]);
            float2 qa = __ldg(&a1[tx]);
            float2 pb = __ldg(&b0[tx]);
            float2 qb = __ldg(&b1[tx]);

            float LLa, LHa, HLa, HHa;
            HAAR(pa.x, pa.y, qa.x, qa.y, LLa, LHa, HLa, HHa);
            float LLb, LHb, HLb, HHb;
            HAAR(pb.x, pb.y, qb.x, qb.y, LLb, LHb, HLb, HHb);

            float* rowa = o1 + (long)ra * 256 + tx;
            rowa[0]          = LLa;
            rowa[65536]      = LHa;
            rowa[2 * 65536]  = HLa;
            rowa[3 * 65536]  = HHa;
            s1[ra * 64 + tx] = LLa;

            float* rowb = o1 + (long)rb * 256 + tx;
            rowb[0]          = LLb;
            rowb[65536]      = LHb;
            rowb[2 * 65536]  = HLb;
            rowb[3 * 65536]  = HHb;
            s1[rb * 64 + tx] = LLb;
        }
    }
    __syncthreads();

    // ---------------- Level 2: s1 -> t2 (32x32 outputs) --------------------
    {
        float* o2 = out + S1 + (long)b * (12 * 16384)
                        + (long)(c * 4) * 16384
                        + (long)(ti * 32) * 128 + tj * 32;

        const int tx = tid & 31;       // column 0..31
        const int ty = tid >> 5;       // 0..7
        const float2* s1v = reinterpret_cast<const float2*>(s1);

        #pragma unroll
        for (int r = ty; r < 32; r += 8) {
            float2 t = s1v[(2 * r) * 32 + tx];
            float2 u = s1v[(2 * r + 1) * 32 + tx];

            float LL, LH, HL, HH;
            HAAR(t.x, t.y, u.x, u.y, LL, LH, HL, HH);

            float* orow = o2 + (long)r * 128 + tx;
            orow[0]          = LL;
            orow[16384]      = LH;
            orow[2 * 16384]  = HL;
            orow[3 * 16384]  = HH;
            s2[r * 32 + tx]  = LL;
        }
    }
    __syncthreads();

    // ---------------- Level 3: s2 -> t3 (16x16 outputs) --------------------
    {
        float* o3 = out + S1 + S2 + (long)b * (12 * 4096)
                        + (long)(c * 4) * 4096
                        + (long)(ti * 16) * 64 + tj * 16;

        const int tx = tid & 15;       // 0..15
        const int ty = tid >> 4;       // 0..15
        const float2* s2v = reinterpret_cast<const float2*>(s2);

        float2 t = s2v[(2 * ty) * 16 + tx];
        float2 u = s2v[(2 * ty + 1) * 16 + tx];

        float LL, LH, HL, HH;
        HAAR(t.x, t.y, u.x, u.y, LL, LH, HL, HH);

        float* orow = o3 + (long)ty * 64 + tx;
        orow[0]         = LL;
        orow[4096]      = LH;
        orow[2 * 4096]  = HL;
        orow[3 * 4096]  = HH;
        s3[ty * 16 + tx] = LL;
    }
    __syncthreads();

    // ---------------- Level 4: s3 -> t4 (8x8 outputs, r/g only) ------------
    if (tid < 64 && c < 2) {
        float* o4 = out + S1 + S2 + S3 + (long)b * (12 * 1024)
                        + (long)(c * 4) * 1024
                        + (long)(ti * 8) * 32 + tj * 8;

        const int tx = tid & 7;        // 0..7
        const int ty = tid >> 3;       // 0..7
        const float2* s3v = reinterpret_cast<const float2*>(s3);

        float2 t = s3v[(2 * ty) * 8 + tx];
        float2 u = s3v[(2 * ty + 1) * 8 + tx];

        float LL, LH, HL, HH;
        HAAR(t.x, t.y, u.x, u.y, LL, LH, HL, HH);

        float* orow = o4 + (long)ty * 32 + tx;
        orow[0]         = LL;
        orow[1024]      = LH;
        orow[2 * 1024]  = HL;
        orow[3 * 1024]  = HH;

        if (c == 1) {                  // b4 = g4 -> channels 8..11
            float* orow2 = orow + 4 * 1024;
            orow2[0]         = LL;
            orow2[1024]      = LH;
            orow2[2 * 1024]  = HL;
            orow2[3 * 1024]  = HH;
        }
    }
}

extern "C" void kernel_launch(void* const* d_in, const int* in_sizes, int n_in,
                              void* d_out, int out_size)
{
    const float* x = (const float*)d_in[0];
    float* out = (float*)d_out;

    dim3 block(256, 1, 1);
    dim3 grid(4, 4, 96);
    dwt_fused_kernel<<<grid, block>>>(x, out);
}